// round 15
// baseline (speedup 1.0000x reference)
#include <cuda_runtime.h>
#include <cuda_bf16.h>
#include <cstdint>

#define Nn  50000
#define Ee  640000
#define HIDd 128
#define Hh  8
#define EFd 16
#define Ll  3
#define NODE_BLOCKS 782
#define NODE_WARPS (NODE_BLOCKS * 8)

typedef unsigned long long u64;

// ---------------- scratch (static device globals; no allocations) ----------------
__device__ __align__(16) float g_xl[Nn * HIDd];
__device__ __align__(16) float g_xr[Nn * HIDd];
__device__ __align__(16) float g_M[Ll * EFd * HIDd];
__device__ __align__(16) float g_c[Ll * HIDd];
__device__ int g_deg[Nn];
__device__ int g_off[Nn + 1];
__device__ int g_cur[Nn];
__device__ int g_srcS[Ee];
__device__ __align__(16) float g_eaS[Ee * EFd];

// ---------------- helpers ----------------
__device__ __forceinline__ u64 pk2(float a, float b) {
    u64 r; asm("mov.b64 %0, {%1, %2};" : "=l"(r) : "f"(a), "f"(b)); return r;
}
__device__ __forceinline__ void upk2(float& a, float& b, u64 v) {
    asm("mov.b64 {%0, %1}, %2;" : "=f"(a), "=f"(b) : "l"(v));
}
__device__ __forceinline__ u64 fma2(u64 a, u64 b, u64 c) {
    u64 d; asm("fma.rn.f32x2 %0, %1, %2, %3;" : "=l"(d) : "l"(a), "l"(b), "l"(c)); return d;
}
__device__ __forceinline__ float ex2(float x) {
    float y; asm("ex2.approx.ftz.f32 %0, %1;" : "=f"(y) : "f"(x)); return y;
}

// ---------------- small utility kernels ----------------
__global__ void copy_kernel(const float4* __restrict__ src, float4* __restrict__ dst, int n4) {
    int i = blockIdx.x * blockDim.x + threadIdx.x;
    if (i < n4) dst[i] = src[i];
}
__global__ void zero_deg_kernel(int* __restrict__ deg) {
    int i = blockIdx.x * blockDim.x + threadIdx.x;
    if (i < Nn) deg[i] = 0;
}
__global__ void hist_kernel(const int* __restrict__ dst, int* __restrict__ deg) {
    int e = blockIdx.x * blockDim.x + threadIdx.x;
    if (e < Ee) atomicAdd(&deg[dst[e]], 1);
}
__global__ void scan_kernel(const int* __restrict__ deg, int* __restrict__ off,
                            int* __restrict__ cur) {
    __shared__ int sums[1024];
    const int t = threadIdx.x;
    const int CH = 49;
    int beg = t * CH;
    int local = 0;
#pragma unroll 1
    for (int i = 0; i < CH; i++) { int idx = beg + i; if (idx < Nn) local += deg[idx]; }
    sums[t] = local;
    __syncthreads();
    int run = local;
    for (int ofs = 1; ofs < 1024; ofs <<= 1) {
        int u = (t >= ofs) ? sums[t - ofs] : 0;
        __syncthreads();
        run += u; sums[t] = run;
        __syncthreads();
    }
    int base = run - local;
#pragma unroll 1
    for (int i = 0; i < CH; i++) {
        int idx = beg + i;
        if (idx < Nn) { off[idx] = base; cur[idx] = base; base += deg[idx]; }
    }
    if (t == 0) off[Nn] = Ee;
}
__global__ void scatter_kernel(const int* __restrict__ srcArr, const int* __restrict__ dst,
                               const float* __restrict__ ea, int* __restrict__ cur,
                               int* __restrict__ srcS, float* __restrict__ eaS) {
    int e = blockIdx.x * blockDim.x + threadIdx.x;
    if (e >= Ee) return;
    int p = atomicAdd(&cur[dst[e]], 1);
    srcS[p] = srcArr[e];
    const float4* s4 = (const float4*)(ea + (size_t)e * EFd);
    float4* d4 = (float4*)(eaS + (size_t)p * EFd);
    d4[0] = s4[0]; d4[1] = s4[1]; d4[2] = s4[2]; d4[3] = s4[3];
}
__global__ void precompute_kernel(const float* __restrict__ Wt, const float* __restrict__ bt,
                                  const float* __restrict__ We,
                                  float* __restrict__ M, float* __restrict__ cv) {
    int l = blockIdx.x;
    int j = threadIdx.x;
    const float* Wel = We + l * HIDd * HIDd;
    float acc[EFd];
#pragma unroll
    for (int k = 0; k < EFd; k++) acc[k] = 0.f;
    float cacc = 0.f;
    for (int i = 0; i < HIDd; i++) {
        float w = Wel[i * HIDd + j];
        cacc = fmaf(bt[i], w, cacc);
#pragma unroll
        for (int k = 0; k < EFd; k++) acc[k] = fmaf(Wt[k * HIDd + i], w, acc[k]);
    }
#pragma unroll
    for (int k = 0; k < EFd; k++) M[l * EFd * HIDd + k * HIDd + j] = acc[k];
    cv[l * HIDd + j] = cacc;
}

// ---------------- SGEMM (R13/R4 version — measured best; FROZEN) ----------------
__global__ void __launch_bounds__(256, 2) gemm128x2(const float* __restrict__ A,
                                                    const float* __restrict__ W0,
                                                    const float* __restrict__ b0,
                                                    float* __restrict__ C0,
                                                    const float* __restrict__ W1,
                                                    const float* __restrict__ b1,
                                                    float* __restrict__ C1,
                                                    int nrows) {
    const float* W    = blockIdx.y ? W1 : W0;
    const float* bias = blockIdx.y ? b1 : b0;
    float*       C    = blockIdx.y ? C1 : C0;

    __shared__ __align__(16) float As[32][132];
    __shared__ __align__(16) float Bs[32][128];
    const int tid = threadIdx.x;
    const int tn = (tid & 15) * 8;
    const int tm = (tid >> 4) * 8;
    const int rowBase = blockIdx.x * 128;

    float acc[8][8];
#pragma unroll
    for (int i = 0; i < 8; i++)
#pragma unroll
        for (int j = 0; j < 8; j++) acc[i][j] = 0.f;

    const int ar = tid >> 3;
    const int ak = (tid & 7) << 2;
    const int bk = tid >> 5;
    const int bn = (tid & 31) << 2;

    for (int kc = 0; kc < 128; kc += 32) {
#pragma unroll
        for (int q = 0; q < 4; q++) {
            int r = ar + q * 32;
            int gr = rowBase + r;
            float4 v = make_float4(0.f, 0.f, 0.f, 0.f);
            if (gr < nrows) v = *(const float4*)(A + (size_t)gr * HIDd + kc + ak);
            As[ak + 0][r] = v.x; As[ak + 1][r] = v.y;
            As[ak + 2][r] = v.z; As[ak + 3][r] = v.w;
        }
#pragma unroll
        for (int q = 0; q < 4; q++) {
            int r = bk + q * 8;
            *(float4*)&Bs[r][bn] = *(const float4*)(W + (size_t)(kc + r) * HIDd + bn);
        }
        __syncthreads();
#pragma unroll
        for (int kk = 0; kk < 32; kk++) {
            float a[8], b[8];
            *(float4*)(a)     = *(const float4*)&As[kk][tm];
            *(float4*)(a + 4) = *(const float4*)&As[kk][tm + 4];
            *(float4*)(b)     = *(const float4*)&Bs[kk][tn];
            *(float4*)(b + 4) = *(const float4*)&Bs[kk][tn + 4];
#pragma unroll
            for (int i = 0; i < 8; i++)
#pragma unroll
                for (int j = 0; j < 8; j++) acc[i][j] = fmaf(a[i], b[j], acc[i][j]);
        }
        __syncthreads();
    }

    float bb[8];
#pragma unroll
    for (int j = 0; j < 8; j++) bb[j] = bias[tn + j];
#pragma unroll
    for (int i = 0; i < 8; i++) {
        int gr = rowBase + tm + i;
        if (gr < nrows) {
            float4 o;
            o.x = acc[i][0] + bb[0]; o.y = acc[i][1] + bb[1];
            o.z = acc[i][2] + bb[2]; o.w = acc[i][3] + bb[3];
            *(float4*)(C + (size_t)gr * HIDd + tn) = o;
            o.x = acc[i][4] + bb[4]; o.y = acc[i][5] + bb[5];
            o.z = acc[i][6] + bb[6]; o.w = acc[i][7] + bb[7];
            *(float4*)(C + (size_t)gr * HIDd + tn + 4) = o;
        }
    }
}

// ---------------- fused node pass: M in regs, warp-strided, 3 edges per iteration ----------------
__global__ void __launch_bounds__(256) node_kernel(const float* __restrict__ eaS,
                                                   const int* __restrict__ srcS,
                                                   const float* __restrict__ xl,
                                                   const float* __restrict__ xr,
                                                   const int* __restrict__ off,
                                                   const float* __restrict__ M,
                                                   const float* __restrict__ cvec,
                                                   const float* __restrict__ att,
                                                   const float* __restrict__ bias_o,
                                                   const float* __restrict__ lng,
                                                   const float* __restrict__ lnb,
                                                   float* __restrict__ x) {
    const int tid = threadIdx.x;
    const int lane = tid & 31;
    const int warpId = (blockIdx.x * 256 + tid) >> 5;

    ulonglong2 Mk[EFd];
    {
        const ulonglong2* M2 = (const ulonglong2*)M;
#pragma unroll
        for (int k = 0; k < EFd; k++) Mk[k] = M2[k * 32 + lane];
    }
    const float4 cv4 = ((const float4*)cvec)[lane];
    float4 av = ((const float4*)att)[lane];
    const float L2E = 1.4426950408889634f;
    av.x *= L2E; av.y *= L2E; av.z *= L2E; av.w *= L2E;

    for (int n = warpId; n < Nn; n += NODE_WARPS) {
        const int beg = off[n];
        const int end = off[n + 1];

        const float4 xrv = ((const float4*)xr)[(size_t)n * 32 + lane];
        float4 pre;
        pre.x = xrv.x + cv4.x; pre.y = xrv.y + cv4.y;
        pre.z = xrv.z + cv4.z; pre.w = xrv.w + cv4.w;

        float4 acc = make_float4(0.f, 0.f, 0.f, 0.f);
        float dsum = 0.f;

        // triple-edge pipeline: slots A,B,C resident; prefetch next triple
        float  evA0 = 0.f, evB0 = 0.f, evC0 = 0.f;
        float4 xlA0 = make_float4(0.f, 0.f, 0.f, 0.f);
        float4 xlB0 = xlA0, xlC0 = xlA0;
        if (beg < end) {
            evA0 = eaS[(size_t)beg * EFd + (lane & 15)];
            xlA0 = ((const float4*)xl)[(size_t)srcS[beg] * 32 + lane];
        }
        if (beg + 1 < end) {
            evB0 = eaS[(size_t)(beg + 1) * EFd + (lane & 15)];
            xlB0 = ((const float4*)xl)[(size_t)srcS[beg + 1] * 32 + lane];
        }
        if (beg + 2 < end) {
            evC0 = eaS[(size_t)(beg + 2) * EFd + (lane & 15)];
            xlC0 = ((const float4*)xl)[(size_t)srcS[beg + 2] * 32 + lane];
        }

        for (int i = beg; i < end; i += 3) {
            float  evA1 = evA0, evB1 = evB0, evC1 = evC0;
            float4 xlA1 = xlA0, xlB1 = xlB0, xlC1 = xlC0;
            if (i + 3 < end) {
                evA1 = eaS[(size_t)(i + 3) * EFd + (lane & 15)];
                xlA1 = ((const float4*)xl)[(size_t)srcS[i + 3] * 32 + lane];
                if (i + 4 < end) {
                    evB1 = eaS[(size_t)(i + 4) * EFd + (lane & 15)];
                    xlB1 = ((const float4*)xl)[(size_t)srcS[i + 4] * 32 + lane];
                }
                if (i + 5 < end) {
                    evC1 = eaS[(size_t)(i + 5) * EFd + (lane & 15)];
                    xlC1 = ((const float4*)xl)[(size_t)srcS[i + 5] * 32 + lane];
                }
            }
            const float  evA = evA0, evB = evB0, evC = evC0;
            const float4 xlA = xlA0, xlB = xlB0, xlC = xlC0;
            const bool hasB = (i + 1 < end);
            const bool hasC = (i + 2 < end);

            // three independent em chains (packed f32x2)
            u64 emA01 = 0, emA23 = 0, emB01 = 0, emB23 = 0, emC01 = 0, emC23 = 0;
#pragma unroll
            for (int k = 0; k < EFd; k++) {
                float aA = __shfl_sync(0xffffffffu, evA, k);
                float aB = __shfl_sync(0xffffffffu, evB, k);
                float aC = __shfl_sync(0xffffffffu, evC, k);
                u64 pA = pk2(aA, aA);
                u64 pB = pk2(aB, aB);
                u64 pC = pk2(aC, aC);
                emA01 = fma2(pA, Mk[k].x, emA01);
                emA23 = fma2(pA, Mk[k].y, emA23);
                emB01 = fma2(pB, Mk[k].x, emB01);
                emB23 = fma2(pB, Mk[k].y, emB23);
                emC01 = fma2(pC, Mk[k].x, emC01);
                emC23 = fma2(pC, Mk[k].y, emC23);
            }
            float a0, a1, a2, a3, b0, b1, b2, b3, c0, c1, c2, c3;
            upk2(a0, a1, emA01); upk2(a2, a3, emA23);
            upk2(b0, b1, emB01); upk2(b2, b3, emB23);
            upk2(c0, c1, emC01); upk2(c2, c3, emC23);

            float mA0 = xlA.x + pre.x + a0, mA1 = xlA.y + pre.y + a1;
            float mA2 = xlA.z + pre.z + a2, mA3 = xlA.w + pre.w + a3;
            float mB0 = xlB.x + pre.x + b0, mB1 = xlB.y + pre.y + b1;
            float mB2 = xlB.z + pre.z + b2, mB3 = xlB.w + pre.w + b3;
            float mC0 = xlC.x + pre.x + c0, mC1 = xlC.y + pre.y + c1;
            float mC2 = xlC.z + pre.z + c2, mC3 = xlC.w + pre.w + c3;
            mA0 = fmaxf(mA0, 0.2f * mA0); mA1 = fmaxf(mA1, 0.2f * mA1);
            mA2 = fmaxf(mA2, 0.2f * mA2); mA3 = fmaxf(mA3, 0.2f * mA3);
            mB0 = fmaxf(mB0, 0.2f * mB0); mB1 = fmaxf(mB1, 0.2f * mB1);
            mB2 = fmaxf(mB2, 0.2f * mB2); mB3 = fmaxf(mB3, 0.2f * mB3);
            mC0 = fmaxf(mC0, 0.2f * mC0); mC1 = fmaxf(mC1, 0.2f * mC1);
            mC2 = fmaxf(mC2, 0.2f * mC2); mC3 = fmaxf(mC3, 0.2f * mC3);

            float pA = mA0 * av.x + mA1 * av.y + mA2 * av.z + mA3 * av.w;
            float pB = mB0 * av.x + mB1 * av.y + mB2 * av.z + mB3 * av.w;
            float pC = mC0 * av.x + mC1 * av.y + mC2 * av.z + mC3 * av.w;
            pA += __shfl_xor_sync(0xffffffffu, pA, 1);
            pB += __shfl_xor_sync(0xffffffffu, pB, 1);
            pC += __shfl_xor_sync(0xffffffffu, pC, 1);
            pA += __shfl_xor_sync(0xffffffffu, pA, 2);
            pB += __shfl_xor_sync(0xffffffffu, pB, 2);
            pC += __shfl_xor_sync(0xffffffffu, pC, 2);

            float wA = ex2(pA);
            float wB = hasB ? ex2(pB) : 0.f;
            float wC = hasC ? ex2(pC) : 0.f;
            dsum += wA + wB + wC;
            acc.x = fmaf(wA, xlA.x, fmaf(wB, xlB.x, fmaf(wC, xlC.x, acc.x)));
            acc.y = fmaf(wA, xlA.y, fmaf(wB, xlB.y, fmaf(wC, xlC.y, acc.y)));
            acc.z = fmaf(wA, xlA.z, fmaf(wB, xlB.z, fmaf(wC, xlC.z, acc.z)));
            acc.w = fmaf(wA, xlA.w, fmaf(wB, xlB.w, fmaf(wC, xlC.w, acc.w)));

            evA0 = evA1; evB0 = evB1; evC0 = evC1;
            xlA0 = xlA1; xlB0 = xlB1; xlC0 = xlC1;
        }

        const float inv = 1.0f / (dsum + 1e-16f);
        float4 bo = ((const float4*)bias_o)[lane];
        float4 o;
        o.x = acc.x * inv + bo.x;
        o.y = acc.y * inv + bo.y;
        o.z = acc.z * inv + bo.z;
        o.w = acc.w * inv + bo.w;

        float s  = o.x + o.y + o.z + o.w;
        float sq = o.x * o.x + o.y * o.y + o.z * o.z + o.w * o.w;
#pragma unroll
        for (int ofs = 16; ofs > 0; ofs >>= 1) {
            s  += __shfl_xor_sync(0xffffffffu, s, ofs);
            sq += __shfl_xor_sync(0xffffffffu, sq, ofs);
        }
        float mu   = s * (1.0f / 128.0f);
        float var  = sq * (1.0f / 128.0f) - mu * mu;
        float rstd = rsqrtf(var + 1e-5f);

        float4 gv = ((const float4*)lng)[lane];
        float4 bv = ((const float4*)lnb)[lane];
        float4 xv = ((float4*)x)[(size_t)n * 32 + lane];
        float y;
        y = gv.x * (o.x - mu) * rstd + bv.x; xv.x += fmaxf(y, 0.f);
        y = gv.y * (o.y - mu) * rstd + bv.y; xv.y += fmaxf(y, 0.f);
        y = gv.z * (o.z - mu) * rstd + bv.z; xv.z += fmaxf(y, 0.f);
        y = gv.w * (o.w - mu) * rstd + bv.w; xv.w += fmaxf(y, 0.f);
        ((float4*)x)[(size_t)n * 32 + lane] = xv;
    }
}

// ---------------- launch ----------------
extern "C" void kernel_launch(void* const* d_in, const int* in_sizes, int n_in,
                              void* d_out, int out_size) {
    const float* x   = (const float*)d_in[0];
    const int*   ei  = (const int*)d_in[2];
    const float* ea  = (const float*)d_in[3];
    const float* Wt  = (const float*)d_in[4];
    const float* bt  = (const float*)d_in[5];
    const float* Wl  = (const float*)d_in[6];
    const float* bl  = (const float*)d_in[7];
    const float* Wr  = (const float*)d_in[8];
    const float* br  = (const float*)d_in[9];
    const float* We  = (const float*)d_in[10];
    const float* att = (const float*)d_in[11];
    const float* bo  = (const float*)d_in[12];
    const float* lg  = (const float*)d_in[13];
    const float* lb  = (const float*)d_in[14];
    float* xbuf = (float*)d_out;

    float *pxl, *pxr, *pM, *pc, *peaS;
    int *pdeg, *poff, *pcur, *psrcS;
    cudaGetSymbolAddress((void**)&pxl,   g_xl);
    cudaGetSymbolAddress((void**)&pxr,   g_xr);
    cudaGetSymbolAddress((void**)&pM,    g_M);
    cudaGetSymbolAddress((void**)&pc,    g_c);
    cudaGetSymbolAddress((void**)&pdeg,  g_deg);
    cudaGetSymbolAddress((void**)&poff,  g_off);
    cudaGetSymbolAddress((void**)&pcur,  g_cur);
    cudaGetSymbolAddress((void**)&psrcS, g_srcS);
    cudaGetSymbolAddress((void**)&peaS,  g_eaS);

    const int* srcArr = ei;
    const int* dstArr = ei + Ee;
    const int n4x = Nn * 32;

    copy_kernel<<<(n4x + 255) / 256, 256>>>((const float4*)x, (float4*)xbuf, n4x);
    precompute_kernel<<<Ll, HIDd>>>(Wt, bt, We, pM, pc);

    zero_deg_kernel<<<(Nn + 255) / 256, 256>>>(pdeg);
    hist_kernel<<<(Ee + 255) / 256, 256>>>(dstArr, pdeg);
    scan_kernel<<<1, 1024>>>(pdeg, poff, pcur);
    scatter_kernel<<<(Ee + 255) / 256, 256>>>(srcArr, dstArr, ea, pcur, psrcS, peaS);

    dim3 ggrid((Nn + 127) / 128, 2);
    for (int l = 0; l < Ll; l++) {
        gemm128x2<<<ggrid, 256>>>(xbuf,
                                  Wl + (size_t)l * HIDd * HIDd, bl + l * HIDd, pxl,
                                  Wr + (size_t)l * HIDd * HIDd, br + l * HIDd, pxr, Nn);
        node_kernel<<<NODE_BLOCKS, 256>>>(peaS, psrcS, pxl, pxr, poff,
                                          pM + (size_t)l * EFd * HIDd, pc + l * HIDd,
                                          att + l * HIDd, bo + l * HIDd,
                                          lg + l * HIDd, lb + l * HIDd, xbuf);
    }
}

// round 17
// speedup vs baseline: 1.1838x; 1.1838x over previous
#include <cuda_runtime.h>
#include <cuda_bf16.h>
#include <cstdint>

#define Nn  50000
#define Ee  640000
#define HIDd 128
#define Hh  8
#define EFd 16
#define Ll  3
#define NODE_BLOCKS 782
#define NODE_WARPS (NODE_BLOCKS * 8)

typedef unsigned long long u64;

// ---------------- scratch (static device globals; no allocations) ----------------
__device__ __align__(16) float g_xl[Nn * HIDd];
__device__ __align__(16) float g_xr[Nn * HIDd];
__device__ __align__(16) float g_M[Ll * EFd * HIDd];
__device__ __align__(16) float g_c[Ll * HIDd];
__device__ int g_deg[Nn];
__device__ int g_off[Nn + 1];
__device__ int g_cur[Nn];
__device__ int g_srcS[Ee];
__device__ __align__(16) float g_eaS[Ee * EFd];

// ---------------- helpers ----------------
__device__ __forceinline__ u64 pk2(float a, float b) {
    u64 r; asm("mov.b64 %0, {%1, %2};" : "=l"(r) : "f"(a), "f"(b)); return r;
}
__device__ __forceinline__ void upk2(float& a, float& b, u64 v) {
    asm("mov.b64 {%0, %1}, %2;" : "=f"(a), "=f"(b) : "l"(v));
}
__device__ __forceinline__ u64 fma2(u64 a, u64 b, u64 c) {
    u64 d; asm("fma.rn.f32x2 %0, %1, %2, %3;" : "=l"(d) : "l"(a), "l"(b), "l"(c)); return d;
}
__device__ __forceinline__ float ex2(float x) {
    float y; asm("ex2.approx.ftz.f32 %0, %1;" : "=f"(y) : "f"(x)); return y;
}

// ---------------- small utility kernels ----------------
__global__ void zero_deg_kernel(int* __restrict__ deg) {
    int i = blockIdx.x * blockDim.x + threadIdx.x;
    if (i < Nn) deg[i] = 0;
}
__global__ void hist_kernel(const int* __restrict__ dst, int* __restrict__ deg) {
    int e = blockIdx.x * blockDim.x + threadIdx.x;
    if (e < Ee) atomicAdd(&deg[dst[e]], 1);
}
__global__ void scan_kernel(const int* __restrict__ deg, int* __restrict__ off,
                            int* __restrict__ cur) {
    __shared__ int sums[1024];
    const int t = threadIdx.x;
    const int CH = 49;
    int beg = t * CH;
    int local = 0;
#pragma unroll 1
    for (int i = 0; i < CH; i++) { int idx = beg + i; if (idx < Nn) local += deg[idx]; }
    sums[t] = local;
    __syncthreads();
    int run = local;
    for (int ofs = 1; ofs < 1024; ofs <<= 1) {
        int u = (t >= ofs) ? sums[t - ofs] : 0;
        __syncthreads();
        run += u; sums[t] = run;
        __syncthreads();
    }
    int base = run - local;
#pragma unroll 1
    for (int i = 0; i < CH; i++) {
        int idx = beg + i;
        if (idx < Nn) { off[idx] = base; cur[idx] = base; base += deg[idx]; }
    }
    if (t == 0) off[Nn] = Ee;
}
__global__ void scatter_kernel(const int* __restrict__ srcArr, const int* __restrict__ dst,
                               const float* __restrict__ ea, int* __restrict__ cur,
                               int* __restrict__ srcS, float* __restrict__ eaS) {
    int e = blockIdx.x * blockDim.x + threadIdx.x;
    if (e >= Ee) return;
    int p = atomicAdd(&cur[dst[e]], 1);
    srcS[p] = srcArr[e];
    const float4* s4 = (const float4*)(ea + (size_t)e * EFd);
    float4* d4 = (float4*)(eaS + (size_t)p * EFd);
    d4[0] = s4[0]; d4[1] = s4[1]; d4[2] = s4[2]; d4[3] = s4[3];
}
__global__ void precompute_kernel(const float* __restrict__ Wt, const float* __restrict__ bt,
                                  const float* __restrict__ We,
                                  float* __restrict__ M, float* __restrict__ cv) {
    int l = blockIdx.x;
    int j = threadIdx.x;
    const float* Wel = We + l * HIDd * HIDd;
    float acc[EFd];
#pragma unroll
    for (int k = 0; k < EFd; k++) acc[k] = 0.f;
    float cacc = 0.f;
    for (int i = 0; i < HIDd; i++) {
        float w = Wel[i * HIDd + j];
        cacc = fmaf(bt[i], w, cacc);
#pragma unroll
        for (int k = 0; k < EFd; k++) acc[k] = fmaf(Wt[k * HIDd + i], w, acc[k]);
    }
#pragma unroll
    for (int k = 0; k < EFd; k++) M[l * EFd * HIDd + k * HIDd + j] = acc[k];
    cv[l * HIDd + j] = cacc;
}

// ---------------- SGEMM (measured best; FROZEN) ----------------
__global__ void __launch_bounds__(256, 2) gemm128x2(const float* __restrict__ A,
                                                    const float* __restrict__ W0,
                                                    const float* __restrict__ b0,
                                                    float* __restrict__ C0,
                                                    const float* __restrict__ W1,
                                                    const float* __restrict__ b1,
                                                    float* __restrict__ C1,
                                                    int nrows) {
    const float* W    = blockIdx.y ? W1 : W0;
    const float* bias = blockIdx.y ? b1 : b0;
    float*       C    = blockIdx.y ? C1 : C0;

    __shared__ __align__(16) float As[32][132];
    __shared__ __align__(16) float Bs[32][128];
    const int tid = threadIdx.x;
    const int tn = (tid & 15) * 8;
    const int tm = (tid >> 4) * 8;
    const int rowBase = blockIdx.x * 128;

    float acc[8][8];
#pragma unroll
    for (int i = 0; i < 8; i++)
#pragma unroll
        for (int j = 0; j < 8; j++) acc[i][j] = 0.f;

    const int ar = tid >> 3;
    const int ak = (tid & 7) << 2;
    const int bk = tid >> 5;
    const int bn = (tid & 31) << 2;

    for (int kc = 0; kc < 128; kc += 32) {
#pragma unroll
        for (int q = 0; q < 4; q++) {
            int r = ar + q * 32;
            int gr = rowBase + r;
            float4 v = make_float4(0.f, 0.f, 0.f, 0.f);
            if (gr < nrows) v = *(const float4*)(A + (size_t)gr * HIDd + kc + ak);
            As[ak + 0][r] = v.x; As[ak + 1][r] = v.y;
            As[ak + 2][r] = v.z; As[ak + 3][r] = v.w;
        }
#pragma unroll
        for (int q = 0; q < 4; q++) {
            int r = bk + q * 8;
            *(float4*)&Bs[r][bn] = *(const float4*)(W + (size_t)(kc + r) * HIDd + bn);
        }
        __syncthreads();
#pragma unroll
        for (int kk = 0; kk < 32; kk++) {
            float a[8], b[8];
            *(float4*)(a)     = *(const float4*)&As[kk][tm];
            *(float4*)(a + 4) = *(const float4*)&As[kk][tm + 4];
            *(float4*)(b)     = *(const float4*)&Bs[kk][tn];
            *(float4*)(b + 4) = *(const float4*)&Bs[kk][tn + 4];
#pragma unroll
            for (int i = 0; i < 8; i++)
#pragma unroll
                for (int j = 0; j < 8; j++) acc[i][j] = fmaf(a[i], b[j], acc[i][j]);
        }
        __syncthreads();
    }

    float bb[8];
#pragma unroll
    for (int j = 0; j < 8; j++) bb[j] = bias[tn + j];
#pragma unroll
    for (int i = 0; i < 8; i++) {
        int gr = rowBase + tm + i;
        if (gr < nrows) {
            float4 o;
            o.x = acc[i][0] + bb[0]; o.y = acc[i][1] + bb[1];
            o.z = acc[i][2] + bb[2]; o.w = acc[i][3] + bb[3];
            *(float4*)(C + (size_t)gr * HIDd + tn) = o;
            o.x = acc[i][4] + bb[4]; o.y = acc[i][5] + bb[5];
            o.z = acc[i][6] + bb[6]; o.w = acc[i][7] + bb[7];
            *(float4*)(C + (size_t)gr * HIDd + tn + 4) = o;
        }
    }
}

// ---------------- fused node pass (R13 dual-edge version — measured best; FROZEN) ----------------
// xin: residual source; xout: output (may alias xin for layers > 0)
__global__ void __launch_bounds__(256) node_kernel(const float* __restrict__ eaS,
                                                   const int* __restrict__ srcS,
                                                   const float* __restrict__ xl,
                                                   const float* __restrict__ xr,
                                                   const int* __restrict__ off,
                                                   const float* __restrict__ M,
                                                   const float* __restrict__ cvec,
                                                   const float* __restrict__ att,
                                                   const float* __restrict__ bias_o,
                                                   const float* __restrict__ lng,
                                                   const float* __restrict__ lnb,
                                                   const float* __restrict__ xin,
                                                   float* __restrict__ xout) {
    const int tid = threadIdx.x;
    const int lane = tid & 31;
    const int warpId = (blockIdx.x * 256 + tid) >> 5;

    ulonglong2 Mk[EFd];
    {
        const ulonglong2* M2 = (const ulonglong2*)M;
#pragma unroll
        for (int k = 0; k < EFd; k++) Mk[k] = M2[k * 32 + lane];
    }
    const float4 cv4 = ((const float4*)cvec)[lane];
    float4 av = ((const float4*)att)[lane];
    const float L2E = 1.4426950408889634f;
    av.x *= L2E; av.y *= L2E; av.z *= L2E; av.w *= L2E;

    for (int n = warpId; n < Nn; n += NODE_WARPS) {
        const int beg = off[n];
        const int end = off[n + 1];

        const float4 xrv = ((const float4*)xr)[(size_t)n * 32 + lane];
        float4 pre;
        pre.x = xrv.x + cv4.x; pre.y = xrv.y + cv4.y;
        pre.z = xrv.z + cv4.z; pre.w = xrv.w + cv4.w;

        float4 acc = make_float4(0.f, 0.f, 0.f, 0.f);
        float dsum = 0.f;

        float  evA0 = 0.f, evB0 = 0.f;
        float4 xlA0 = make_float4(0.f, 0.f, 0.f, 0.f);
        float4 xlB0 = make_float4(0.f, 0.f, 0.f, 0.f);
        if (beg < end) {
            evA0 = eaS[(size_t)beg * EFd + (lane & 15)];
            xlA0 = ((const float4*)xl)[(size_t)srcS[beg] * 32 + lane];
        }
        if (beg + 1 < end) {
            evB0 = eaS[(size_t)(beg + 1) * EFd + (lane & 15)];
            xlB0 = ((const float4*)xl)[(size_t)srcS[beg + 1] * 32 + lane];
        }

        for (int i = beg; i < end; i += 2) {
            float  evA1 = evA0, evB1 = evB0;
            float4 xlA1 = xlA0, xlB1 = xlB0;
            if (i + 2 < end) {
                evA1 = eaS[(size_t)(i + 2) * EFd + (lane & 15)];
                xlA1 = ((const float4*)xl)[(size_t)srcS[i + 2] * 32 + lane];
                if (i + 3 < end) {
                    evB1 = eaS[(size_t)(i + 3) * EFd + (lane & 15)];
                    xlB1 = ((const float4*)xl)[(size_t)srcS[i + 3] * 32 + lane];
                }
            }
            const float  evA = evA0, evB = evB0;
            const float4 xlA = xlA0, xlB = xlB0;
            const bool hasB = (i + 1 < end);

            u64 emA01 = 0, emA23 = 0, emB01 = 0, emB23 = 0;
#pragma unroll
            for (int k = 0; k < EFd; k++) {
                float aA = __shfl_sync(0xffffffffu, evA, k);
                float aB = __shfl_sync(0xffffffffu, evB, k);
                u64 pA = pk2(aA, aA);
                u64 pB = pk2(aB, aB);
                emA01 = fma2(pA, Mk[k].x, emA01);
                emA23 = fma2(pA, Mk[k].y, emA23);
                emB01 = fma2(pB, Mk[k].x, emB01);
                emB23 = fma2(pB, Mk[k].y, emB23);
            }
            float a0, a1, a2, a3, b0, b1, b2, b3;
            upk2(a0, a1, emA01); upk2(a2, a3, emA23);
            upk2(b0, b1, emB01); upk2(b2, b3, emB23);

            float mA0 = xlA.x + pre.x + a0, mA1 = xlA.y + pre.y + a1;
            float mA2 = xlA.z + pre.z + a2, mA3 = xlA.w + pre.w + a3;
            float mB0 = xlB.x + pre.x + b0, mB1 = xlB.y + pre.y + b1;
            float mB2 = xlB.z + pre.z + b2, mB3 = xlB.w + pre.w + b3;
            mA0 = fmaxf(mA0, 0.2f * mA0); mA1 = fmaxf(mA1, 0.2f * mA1);
            mA2 = fmaxf(mA2, 0.2f * mA2); mA3 = fmaxf(mA3, 0.2f * mA3);
            mB0 = fmaxf(mB0, 0.2f * mB0); mB1 = fmaxf(mB1, 0.2f * mB1);
            mB2 = fmaxf(mB2, 0.2f * mB2); mB3 = fmaxf(mB3, 0.2f * mB3);

            float pA = mA0 * av.x + mA1 * av.y + mA2 * av.z + mA3 * av.w;
            float pB = mB0 * av.x + mB1 * av.y + mB2 * av.z + mB3 * av.w;
            pA += __shfl_xor_sync(0xffffffffu, pA, 1);
            pB += __shfl_xor_sync(0xffffffffu, pB, 1);
            pA += __shfl_xor_sync(0xffffffffu, pA, 2);
            pB += __shfl_xor_sync(0xffffffffu, pB, 2);

            float wA = ex2(pA);
            float wB = hasB ? ex2(pB) : 0.f;
            dsum += wA + wB;
            acc.x = fmaf(wA, xlA.x, fmaf(wB, xlB.x, acc.x));
            acc.y = fmaf(wA, xlA.y, fmaf(wB, xlB.y, acc.y));
            acc.z = fmaf(wA, xlA.z, fmaf(wB, xlB.z, acc.z));
            acc.w = fmaf(wA, xlA.w, fmaf(wB, xlB.w, acc.w));

            evA0 = evA1; evB0 = evB1;
            xlA0 = xlA1; xlB0 = xlB1;
        }

        const float inv = 1.0f / (dsum + 1e-16f);
        float4 bo = ((const float4*)bias_o)[lane];
        float4 o;
        o.x = acc.x * inv + bo.x;
        o.y = acc.y * inv + bo.y;
        o.z = acc.z * inv + bo.z;
        o.w = acc.w * inv + bo.w;

        float s  = o.x + o.y + o.z + o.w;
        float sq = o.x * o.x + o.y * o.y + o.z * o.z + o.w * o.w;
#pragma unroll
        for (int ofs = 16; ofs > 0; ofs >>= 1) {
            s  += __shfl_xor_sync(0xffffffffu, s, ofs);
            sq += __shfl_xor_sync(0xffffffffu, sq, ofs);
        }
        float mu   = s * (1.0f / 128.0f);
        float var  = sq * (1.0f / 128.0f) - mu * mu;
        float rstd = rsqrtf(var + 1e-5f);

        float4 gv = ((const float4*)lng)[lane];
        float4 bv = ((const float4*)lnb)[lane];
        float4 xv = ((const float4*)xin)[(size_t)n * 32 + lane];
        float y;
        y = gv.x * (o.x - mu) * rstd + bv.x; xv.x += fmaxf(y, 0.f);
        y = gv.y * (o.y - mu) * rstd + bv.y; xv.y += fmaxf(y, 0.f);
        y = gv.z * (o.z - mu) * rstd + bv.z; xv.z += fmaxf(y, 0.f);
        y = gv.w * (o.w - mu) * rstd + bv.w; xv.w += fmaxf(y, 0.f);
        ((float4*)xout)[(size_t)n * 32 + lane] = xv;
    }
}

// ---------------- launch ----------------
extern "C" void kernel_launch(void* const* d_in, const int* in_sizes, int n_in,
                              void* d_out, int out_size) {
    const float* x   = (const float*)d_in[0];
    const int*   ei  = (const int*)d_in[2];
    const float* ea  = (const float*)d_in[3];
    const float* Wt  = (const float*)d_in[4];
    const float* bt  = (const float*)d_in[5];
    const float* Wl  = (const float*)d_in[6];
    const float* bl  = (const float*)d_in[7];
    const float* Wr  = (const float*)d_in[8];
    const float* br  = (const float*)d_in[9];
    const float* We  = (const float*)d_in[10];
    const float* att = (const float*)d_in[11];
    const float* bo  = (const float*)d_in[12];
    const float* lg  = (const float*)d_in[13];
    const float* lb  = (const float*)d_in[14];
    float* xbuf = (float*)d_out;

    float *pxl, *pxr, *pM, *pc, *peaS;
    int *pdeg, *poff, *pcur, *psrcS;
    cudaGetSymbolAddress((void**)&pxl,   g_xl);
    cudaGetSymbolAddress((void**)&pxr,   g_xr);
    cudaGetSymbolAddress((void**)&pM,    g_M);
    cudaGetSymbolAddress((void**)&pc,    g_c);
    cudaGetSymbolAddress((void**)&pdeg,  g_deg);
    cudaGetSymbolAddress((void**)&poff,  g_off);
    cudaGetSymbolAddress((void**)&pcur,  g_cur);
    cudaGetSymbolAddress((void**)&psrcS, g_srcS);
    cudaGetSymbolAddress((void**)&peaS,  g_eaS);

    const int* srcArr = ei;
    const int* dstArr = ei + Ee;

    precompute_kernel<<<Ll, HIDd>>>(Wt, bt, We, pM, pc);

    zero_deg_kernel<<<(Nn + 255) / 256, 256>>>(pdeg);
    hist_kernel<<<(Ee + 255) / 256, 256>>>(dstArr, pdeg);
    scan_kernel<<<1, 1024>>>(pdeg, poff, pcur);
    scatter_kernel<<<(Ee + 255) / 256, 256>>>(srcArr, dstArr, ea, pcur, psrcS, peaS);

    dim3 ggrid((Nn + 127) / 128, 2);
    for (int l = 0; l < Ll; l++) {
        const float* xcur = (l == 0) ? x : xbuf;   // layer-0 reads harness input directly
        gemm128x2<<<ggrid, 256>>>(xcur,
                                  Wl + (size_t)l * HIDd * HIDd, bl + l * HIDd, pxl,
                                  Wr + (size_t)l * HIDd * HIDd, br + l * HIDd, pxr, Nn);
        node_kernel<<<NODE_BLOCKS, 256>>>(peaS, psrcS, pxl, pxr, poff,
                                          pM + (size_t)l * EFd * HIDd, pc + l * HIDd,
                                          att + l * HIDd, bo + l * HIDd,
                                          lg + l * HIDd, lb + l * HIDd,
                                          xcur, xbuf);
    }
}